// round 7
// baseline (speedup 1.0000x reference)
#include <cuda_runtime.h>
#include <cuda_fp16.h>
#include <cstdint>

#define B_   128
#define N_   512
#define FIN  128
#define FOUT 64

// Scratch (allocation-free rule: __device__ globals)
__device__ __half   g_hh[B_ * N_ * FOUT];       // h fp16, row-major [row][f]
__device__ float    g_s[B_ * N_];
__device__ float    g_t[B_ * N_];
__device__ uint32_t g_mask[B_ * N_ * 16];       // adj bitmask: 16 words/row (512 bits)

// ---------------------------------------------------------------------------
// PTX helpers
// ---------------------------------------------------------------------------
__device__ __forceinline__ uint32_t smem_u32(const void* p) {
    return (uint32_t)__cvta_generic_to_shared(p);
}
__device__ __forceinline__ void ldsm_x4(uint32_t& r0, uint32_t& r1, uint32_t& r2, uint32_t& r3, uint32_t addr) {
    asm volatile("ldmatrix.sync.aligned.m8n8.x4.shared.b16 {%0,%1,%2,%3}, [%4];\n"
                 : "=r"(r0), "=r"(r1), "=r"(r2), "=r"(r3) : "r"(addr));
}
__device__ __forceinline__ void ldsm_x4t(uint32_t& r0, uint32_t& r1, uint32_t& r2, uint32_t& r3, uint32_t addr) {
    asm volatile("ldmatrix.sync.aligned.m8n8.x4.trans.shared.b16 {%0,%1,%2,%3}, [%4];\n"
                 : "=r"(r0), "=r"(r1), "=r"(r2), "=r"(r3) : "r"(addr));
}
__device__ __forceinline__ void mma16816(float* d, const uint32_t* a, uint32_t b0, uint32_t b1) {
    asm volatile("mma.sync.aligned.m16n8k16.row.col.f32.f16.f16.f32 "
                 "{%0,%1,%2,%3},{%4,%5,%6,%7},{%8,%9},{%0,%1,%2,%3};\n"
                 : "+f"(d[0]), "+f"(d[1]), "+f"(d[2]), "+f"(d[3])
                 : "r"(a[0]), "r"(a[1]), "r"(a[2]), "r"(a[3]), "r"(b0), "r"(b1));
}
__device__ __forceinline__ void cp_async16(uint32_t saddr, const void* gptr) {
    asm volatile("cp.async.cg.shared.global [%0], [%1], 16;\n" :: "r"(saddr), "l"(gptr));
}
#define CP_COMMIT() asm volatile("cp.async.commit_group;\n" ::: "memory")
#define CP_WAIT0()  asm volatile("cp.async.wait_group 0;\n" ::: "memory")

// ---------------------------------------------------------------------------
// Kernel M: pack adj int32 -> bitmask (1 bit/edge). Pure streaming.
// Warp handles 2 rows; per 128-col span: int4 LDG -> nibble -> shfl-OR pack.
// ---------------------------------------------------------------------------
__global__ void __launch_bounds__(256) maskpack_kernel(const int* __restrict__ adj)
{
    const int warp = threadIdx.x >> 5;
    const int lane = threadIdx.x & 31;
    const size_t row0 = (size_t)blockIdx.x * 16 + warp * 2;

#pragma unroll
    for (int rr = 0; rr < 2; rr++) {
        const size_t row = row0 + rr;
        const int4* arow = (const int4*)(adj + row * N_);
#pragma unroll
        for (int sp = 0; sp < 4; sp++) {
            int4 av = arow[sp * 32 + lane];
            uint32_t nib = (uint32_t)(av.x > 0) | ((uint32_t)(av.y > 0) << 1)
                         | ((uint32_t)(av.z > 0) << 2) | ((uint32_t)(av.w > 0) << 3);
            uint32_t v = nib << ((lane & 7) * 4);
            v |= __shfl_xor_sync(0xffffffffu, v, 1);
            v |= __shfl_xor_sync(0xffffffffu, v, 2);
            v |= __shfl_xor_sync(0xffffffffu, v, 4);
            if ((lane & 7) == 0)
                g_mask[row * 16 + sp * 4 + (lane >> 3)] = v;
        }
    }
}

// ---------------------------------------------------------------------------
// Kernel A: h = X @ W on tensor cores (fp16 3-term split: hihi + hilo + lohi).
// Block: 128 rows x 64 cols, K=128 in 2 halves. 8 warps, one m16 tile each.
// Epilogue: h fp16 store + fused s = h.a_src, t = h.a_dst.
// ---------------------------------------------------------------------------
#define XS 72   // halves stride (64+8): 144B rows, 16B-aligned
#define WS 72

__global__ void __launch_bounds__(256, 3) gemm1_kernel(
    const float* __restrict__ X, const float* __restrict__ W,
    const float* __restrict__ a)
{
    extern __shared__ __half smh[];
    __half* Xhi = smh;                 // 128 x 72
    __half* Xlo = Xhi + 128 * XS;      // 128 x 72
    __half* Whi = Xlo + 128 * XS;      // 64 x 72
    __half* Wlo = Whi + 64 * WS;       // 64 x 72

    const int tid  = threadIdx.x;
    const int warp = tid >> 5;
    const int lane = tid & 31;
    const int m0   = blockIdx.x * 128;

    const int lrow16 = lane & 15;
    const int lhalf  = lane >> 4;
    const uint32_t aHi = smem_u32(Xhi + (warp * 16 + lrow16) * XS + lhalf * 8);
    const uint32_t aLo = smem_u32(Xlo + (warp * 16 + lrow16) * XS + lhalf * 8);
    const uint32_t bHi = smem_u32(Whi + lrow16 * WS + lhalf * 8);
    const uint32_t bLo = smem_u32(Wlo + lrow16 * WS + lhalf * 8);

    float acc[8][4] = {};

#pragma unroll
    for (int kh = 0; kh < 2; kh++) {
        // X half 128x64: convert to hi/lo fp16
#pragma unroll
        for (int p = 0; p < 8; p++) {
            int u  = p * 256 + tid;
            int r  = u >> 4;
            int c4 = (u & 15) * 4;
            float4 xv = *(const float4*)(X + (size_t)(m0 + r) * FIN + kh * 64 + c4);
            __half h4[4], l4[4];
            h4[0] = __float2half(xv.x); l4[0] = __float2half(xv.x - __half2float(h4[0]));
            h4[1] = __float2half(xv.y); l4[1] = __float2half(xv.y - __half2float(h4[1]));
            h4[2] = __float2half(xv.z); l4[2] = __float2half(xv.z - __half2float(h4[2]));
            h4[3] = __float2half(xv.w); l4[3] = __float2half(xv.w - __half2float(h4[3]));
            *(uint2*)(Xhi + r * XS + c4) = *(uint2*)h4;
            *(uint2*)(Xlo + r * XS + c4) = *(uint2*)l4;
        }
        // W half 64x64: convert to hi/lo fp16
#pragma unroll
        for (int p = 0; p < 4; p++) {
            int u  = p * 256 + tid;
            int k  = u >> 4;
            int c4 = (u & 15) * 4;
            float4 wv = *(const float4*)(W + (size_t)(kh * 64 + k) * FOUT + c4);
            __half h4[4], l4[4];
            h4[0] = __float2half(wv.x); l4[0] = __float2half(wv.x - __half2float(h4[0]));
            h4[1] = __float2half(wv.y); l4[1] = __float2half(wv.y - __half2float(h4[1]));
            h4[2] = __float2half(wv.z); l4[2] = __float2half(wv.z - __half2float(h4[2]));
            h4[3] = __float2half(wv.w); l4[3] = __float2half(wv.w - __half2float(h4[3]));
            *(uint2*)(Whi + k * WS + c4) = *(uint2*)h4;
            *(uint2*)(Wlo + k * WS + c4) = *(uint2*)l4;
        }
        __syncthreads();

#pragma unroll
        for (int ks = 0; ks < 4; ks++) {
            const uint32_t aOff = (uint32_t)(ks * 16) * 2;
            const uint32_t bOff = (uint32_t)(ks * 16) * WS * 2;
            uint32_t ah[4], al[4];
            ldsm_x4(ah[0], ah[1], ah[2], ah[3], aHi + aOff);
            ldsm_x4(al[0], al[1], al[2], al[3], aLo + aOff);
#pragma unroll
            for (int ng = 0; ng < 4; ng++) {
                uint32_t bh[4], bl[4];
                ldsm_x4t(bh[0], bh[1], bh[2], bh[3], bHi + bOff + ng * 32);
                ldsm_x4t(bl[0], bl[1], bl[2], bl[3], bLo + bOff + ng * 32);
                mma16816(acc[ng * 2],     ah, bh[0], bh[1]);
                mma16816(acc[ng * 2],     ah, bl[0], bl[1]);
                mma16816(acc[ng * 2],     al, bh[0], bh[1]);
                mma16816(acc[ng * 2 + 1], ah, bh[2], bh[3]);
                mma16816(acc[ng * 2 + 1], ah, bl[2], bl[3]);
                mma16816(acc[ng * 2 + 1], al, bh[2], bh[3]);
            }
        }
        __syncthreads();
    }

    // Epilogue: h fp16 store + fused s/t
    const int gid = lane >> 2;
    const int tg  = lane & 3;
    const size_t rA = (size_t)m0 + warp * 16 + gid;
    const size_t rB = rA + 8;

    float spA = 0.f, tpA = 0.f, spB = 0.f, tpB = 0.f;
#pragma unroll
    for (int j = 0; j < 8; j++) {
        int col = j * 8 + tg * 2;
        float a0 = __ldg(a + col), a1 = __ldg(a + col + 1);
        float d0 = __ldg(a + 64 + col), d1 = __ldg(a + 64 + col + 1);

        __half2 hA = __floats2half2_rn(acc[j][0], acc[j][1]);
        __half2 hB = __floats2half2_rn(acc[j][2], acc[j][3]);
        *(uint32_t*)(g_hh + rA * FOUT + col) = *(uint32_t*)&hA;
        *(uint32_t*)(g_hh + rB * FOUT + col) = *(uint32_t*)&hB;

        spA += acc[j][0] * a0 + acc[j][1] * a1;
        tpA += acc[j][0] * d0 + acc[j][1] * d1;
        spB += acc[j][2] * a0 + acc[j][3] * a1;
        tpB += acc[j][2] * d0 + acc[j][3] * d1;
    }
#pragma unroll
    for (int o = 1; o <= 2; o <<= 1) {
        spA += __shfl_xor_sync(0xffffffffu, spA, o);
        tpA += __shfl_xor_sync(0xffffffffu, tpA, o);
        spB += __shfl_xor_sync(0xffffffffu, spB, o);
        tpB += __shfl_xor_sync(0xffffffffu, tpB, o);
    }
    if (tg == 0) {
        g_s[rA] = spA; g_t[rA] = tpA;
        g_s[rB] = spB; g_t[rB] = tpB;
    }
}

// ---------------------------------------------------------------------------
// Kernel B: chunked masked-softmax (bitmask from smem) + tensor-core att@h.
// Pipelined: hs double-buffered cp.async, attC double-buffered, 1 barrier/chunk.
// ---------------------------------------------------------------------------
#define ATT_S 72
#define HS_S  72

__global__ void __launch_bounds__(256, 5) attn_kernel(float* __restrict__ out)
{
    extern __shared__ char smraw[];
    float* t_sh = (float*)smraw;                   // 512
    float* inv  = t_sh + 512;                      // 32
    float* wmax = inv + 32;                        // 8
    uint32_t* mask_sh = (uint32_t*)(wmax + 8);     // 32 rows x 16 words
    __half* attC = (__half*)(mask_sh + 512);       // 2 x 32 x 72
    __half* hsC  = attC + 2 * 32 * ATT_S;          // 2 x 64 x 72

    const int b    = blockIdx.y;
    const int r0   = blockIdx.x * 32;
    const int tid  = threadIdx.x;
    const int warp = tid >> 5;
    const int lane = tid & 31;

    // hs cp.async per-thread targets
    const int ld_row = tid >> 3;
    const int ld_off = (tid & 7) * 8;
    const __half* hb = g_hh + (size_t)b * N_ * FOUT;
    const uint32_t hsBase = smem_u32(hsC);

    // prologue: stream hs chunk 0 into buf 0
    cp_async16(hsBase + (uint32_t)((ld_row)      * HS_S + ld_off) * 2, hb + (size_t)(ld_row)      * FOUT + ld_off);
    cp_async16(hsBase + (uint32_t)((ld_row + 32) * HS_S + ld_off) * 2, hb + (size_t)(ld_row + 32) * FOUT + ld_off);
    CP_COMMIT();

    // mask for this 32-row tile: 512 words
    mask_sh[tid]       = g_mask[((size_t)b * N_ + r0) * 16 + tid];
    mask_sh[tid + 256] = g_mask[((size_t)b * N_ + r0) * 16 + tid + 256];

    float t0 = g_t[b * N_ + tid];
    float t1 = g_t[b * N_ + tid + 256];
    t_sh[tid]       = t0;
    t_sh[tid + 256] = t1;

    float m2 = fmaxf(t0, t1);
#pragma unroll
    for (int o = 16; o; o >>= 1) m2 = fmaxf(m2, __shfl_xor_sync(0xffffffffu, m2, o));
    if (lane == 0) wmax[warp] = m2;
    __syncthreads();
    const float maxT = fmaxf(fmaxf(fmaxf(wmax[0], wmax[1]), fmaxf(wmax[2], wmax[3])),
                             fmaxf(fmaxf(wmax[4], wmax[5]), fmaxf(wmax[6], wmax[7])));

    // per-row constants (warp owns local rows warp*4 .. +3)
    float s_r[4], mx_r[4], sum_r[4];
#pragma unroll
    for (int rr = 0; rr < 4; rr++) {
        int grow = r0 + warp * 4 + rr;
        float s  = g_s[b * N_ + grow];
        float pm = s + maxT;
        s_r[rr]  = s;
        mx_r[rr] = pm > 0.f ? pm : 0.2f * pm;
        sum_r[rr] = 0.f;
    }

    // fragment addressing
    const int mtile  = warp >> 2;
    const int ntg0   = (warp & 3) * 2;
    const int lrow16 = lane & 15;
    const int lhalf  = lane >> 4;
    const uint32_t aBase = smem_u32(attC + (mtile * 16 + lrow16) * ATT_S + lhalf * 8);
    const uint32_t bBase = smem_u32(hsC + lrow16 * HS_S + (ntg0 + lhalf) * 8);
    const uint32_t attBufB = (uint32_t)(32 * ATT_S) * 2;
    const uint32_t hsBufB  = (uint32_t)(64 * HS_S) * 2;

    float acc0[4] = {0.f, 0.f, 0.f, 0.f};
    float acc1[4] = {0.f, 0.f, 0.f, 0.f};

    const uint32_t mword = lane >> 4;          // word offset within chunk pair
    const uint32_t mbit  = (lane & 15) * 2;    // bit position of first col

    for (int c = 0; c < 8; c++) {
        const int k0  = c * 64;
        const int buf = c & 1;

        // phase-1: weights for 32 rows x 64 cols -> attC[buf]
        __half* attW = attC + buf * 32 * ATT_S;
#pragma unroll
        for (int rr = 0; rr < 4; rr++) {
            int r = warp * 4 + rr;
            uint32_t mw = mask_sh[r * 16 + c * 2 + mword];
            float2 tv = *(const float2*)(t_sh + k0 + lane * 2);
            float e0 = s_r[rr] + tv.x; e0 = fmaxf(e0, 0.2f * e0);
            float e1 = s_r[rr] + tv.y; e1 = fmaxf(e1, 0.2f * e1);
            float w0 = ((mw >> mbit) & 1u)        ? __expf(e0 - mx_r[rr]) : 0.f;
            float w1 = ((mw >> (mbit + 1)) & 1u)  ? __expf(e1 - mx_r[rr]) : 0.f;
            sum_r[rr] += w0 + w1;
            __half2 p = __floats2half2_rn(w0, w1);
            *(uint32_t*)(attW + r * ATT_S + lane * 2) = *(uint32_t*)&p;
        }

        CP_WAIT0();            // hs[c] landed
        __syncthreads();       // attC[buf] + hs[buf] visible

        // stream hs chunk c+1 into the other buffer
        if (c < 7) {
            const __half* hn = hb + (size_t)(k0 + 64) * FOUT;
            uint32_t dst = hsBase + (1 - buf) * hsBufB;
            cp_async16(dst + (uint32_t)((ld_row)      * HS_S + ld_off) * 2, hn + (size_t)(ld_row)      * FOUT + ld_off);
            cp_async16(dst + (uint32_t)((ld_row + 32) * HS_S + ld_off) * 2, hn + (size_t)(ld_row + 32) * FOUT + ld_off);
            CP_COMMIT();
        }

        // MMA: C[32,64] += attC[buf] @ hsC[buf]
        const uint32_t aA = aBase + buf * attBufB;
        const uint32_t bA = bBase + buf * hsBufB;
#pragma unroll
        for (int ks = 0; ks < 4; ks++) {
            const uint32_t aOff = (uint32_t)(ks * 16) * 2;
            const uint32_t bOff = (uint32_t)(ks * 16) * HS_S * 2;
            uint32_t av[4], b0, b1, b2, b3;
            ldsm_x4(av[0], av[1], av[2], av[3], aA + aOff);
            ldsm_x4t(b0, b1, b2, b3, bA + bOff);
            mma16816(acc0, av, b0, b1);
            mma16816(acc1, av, b2, b3);
        }
    }

    // row sums -> inv
#pragma unroll
    for (int rr = 0; rr < 4; rr++) {
        float sum = sum_r[rr];
#pragma unroll
        for (int o = 16; o; o >>= 1) sum += __shfl_xor_sync(0xffffffffu, sum, o);
        if (lane == 0) inv[warp * 4 + rr] = 1.0f / sum;
    }
    __syncthreads();

    // epilogue: normalize + leaky_relu(0.01) + store
    const int gid = lane >> 2;
    const int tg  = lane & 3;
    const int rA  = mtile * 16 + gid;
    const int rB  = rA + 8;
    const float invA = inv[rA];
    const float invB = inv[rB];

#pragma unroll
    for (int nt = 0; nt < 2; nt++) {
        float* acc = nt ? acc1 : acc0;
        int col = (ntg0 + nt) * 8 + tg * 2;
        float v;
        float2 oA, oB;
        v = acc[0] * invA; oA.x = v > 0.f ? v : 0.01f * v;
        v = acc[1] * invA; oA.y = v > 0.f ? v : 0.01f * v;
        v = acc[2] * invB; oB.x = v > 0.f ? v : 0.01f * v;
        v = acc[3] * invB; oB.y = v > 0.f ? v : 0.01f * v;
        *(float2*)(out + ((size_t)b * N_ + r0 + rA) * FOUT + col) = oA;
        *(float2*)(out + ((size_t)b * N_ + r0 + rB) * FOUT + col) = oB;
    }
}

// ---------------------------------------------------------------------------
extern "C" void kernel_launch(void* const* d_in, const int* in_sizes, int n_in,
                              void* d_out, int out_size)
{
    const float* X   = (const float*)d_in[0];
    const int*   adj = (const int*)  d_in[1];
    const float* W   = (const float*)d_in[2];
    const float* a   = (const float*)d_in[3];
    float* out = (float*)d_out;

    maskpack_kernel<<<(B_ * N_) / 16, 256>>>(adj);

    size_t smA = (size_t)(2 * 128 * XS + 2 * 64 * WS) * sizeof(__half);   // 55.3 KB
    cudaFuncSetAttribute(gemm1_kernel, cudaFuncAttributeMaxDynamicSharedMemorySize, (int)smA);
    gemm1_kernel<<<(B_ * N_) / 128, 256, smA>>>(X, W, a);

    size_t smB = (512 + 32 + 8) * sizeof(float) + 512 * sizeof(uint32_t)
               + (size_t)(2 * 32 * ATT_S + 2 * 64 * HS_S) * sizeof(__half);  // ~31.9 KB
    cudaFuncSetAttribute(attn_kernel, cudaFuncAttributeMaxDynamicSharedMemorySize, (int)smB);
    attn_kernel<<<dim3(N_ / 32, B_), 256, smB>>>(out);
}

// round 8
// speedup vs baseline: 1.0155x; 1.0155x over previous
#include <cuda_runtime.h>
#include <cuda_fp16.h>
#include <cstdint>

#define B_   128
#define N_   512
#define FIN  128
#define FOUT 64
#define L2E  1.4426950408889634f

// Scratch (allocation-free rule: __device__ globals)
__device__ __half   g_hh[B_ * N_ * FOUT];       // h fp16, row-major [row][f]
__device__ float    g_s[B_ * N_];               // s * log2(e)
__device__ float    g_t[B_ * N_];               // t * log2(e)
__device__ uint32_t g_mask[B_ * N_ * 16];       // adj bitmask: 16 words/row

// ---------------------------------------------------------------------------
// PTX helpers
// ---------------------------------------------------------------------------
__device__ __forceinline__ uint32_t smem_u32(const void* p) {
    return (uint32_t)__cvta_generic_to_shared(p);
}
__device__ __forceinline__ float ex2f(float x) {
    float y;
    asm("ex2.approx.f32 %0, %1;\n" : "=f"(y) : "f"(x));
    return y;
}
__device__ __forceinline__ void ldsm_x4(uint32_t& r0, uint32_t& r1, uint32_t& r2, uint32_t& r3, uint32_t addr) {
    asm volatile("ldmatrix.sync.aligned.m8n8.x4.shared.b16 {%0,%1,%2,%3}, [%4];\n"
                 : "=r"(r0), "=r"(r1), "=r"(r2), "=r"(r3) : "r"(addr));
}
__device__ __forceinline__ void ldsm_x4t(uint32_t& r0, uint32_t& r1, uint32_t& r2, uint32_t& r3, uint32_t addr) {
    asm volatile("ldmatrix.sync.aligned.m8n8.x4.trans.shared.b16 {%0,%1,%2,%3}, [%4];\n"
                 : "=r"(r0), "=r"(r1), "=r"(r2), "=r"(r3) : "r"(addr));
}
__device__ __forceinline__ void mma16816(float* d, const uint32_t* a, uint32_t b0, uint32_t b1) {
    asm volatile("mma.sync.aligned.m16n8k16.row.col.f32.f16.f16.f32 "
                 "{%0,%1,%2,%3},{%4,%5,%6,%7},{%8,%9},{%0,%1,%2,%3};\n"
                 : "+f"(d[0]), "+f"(d[1]), "+f"(d[2]), "+f"(d[3])
                 : "r"(a[0]), "r"(a[1]), "r"(a[2]), "r"(a[3]), "r"(b0), "r"(b1));
}
__device__ __forceinline__ void cp_async16(uint32_t saddr, const void* gptr) {
    asm volatile("cp.async.cg.shared.global [%0], [%1], 16;\n" :: "r"(saddr), "l"(gptr));
}
#define CP_COMMIT() asm volatile("cp.async.commit_group;\n" ::: "memory")
#define CP_WAIT0()  asm volatile("cp.async.wait_group 0;\n" ::: "memory")

// ---------------------------------------------------------------------------
// Kernel A: h = X @ W  (SIMT, K in 2 halves)  +  FUSED adj bit-packing
//   + fused s = (h.a_src)*log2e, t = (h.a_dst)*log2e
// adj packing: per kh-quarter (16 k), warp qi*8+warp packs one adj row
// (coalesced int4 loads issued BEFORE the FFMA chunk; shfl-OR; 16 regs).
// ---------------------------------------------------------------------------
__global__ void __launch_bounds__(256) gemm1_kernel(
    const float* __restrict__ X, const float* __restrict__ W,
    const float* __restrict__ a, const int* __restrict__ adj)
{
    extern __shared__ float sm[];
    float* Xs = sm;               // [64][68]
    float* Ws = sm + 64 * 68;     // [128][64]

    const int tid  = threadIdx.x;
    const int warp = tid >> 5;
    const int lane = tid & 31;
    const int m0   = blockIdx.x * 64;

#pragma unroll
    for (int p = 0; p < 8; p++) {
        int u  = p * 256 + tid;
        int k  = u >> 4;
        int c4 = (u & 15) * 4;
        *(float4*)(Ws + k * 64 + c4) = *(const float4*)(W + k * 64 + c4);
    }

    const int tx = tid & 15;
    const int ty = tid >> 4;
    float acc[4][4] = {};

#pragma unroll
    for (int kh = 0; kh < 2; kh++) {
#pragma unroll
        for (int p = 0; p < 4; p++) {
            int u  = p * 256 + tid;
            int r  = u >> 4;
            int k4 = (u & 15) * 4;
            *(float4*)(Xs + r * 68 + k4) =
                *(const float4*)(X + (size_t)(m0 + r) * FIN + kh * 64 + k4);
        }
        __syncthreads();

#pragma unroll
        for (int q = 0; q < 4; q++) {
            // --- issue adj loads for row (qi*8 + warp), fully coalesced ---
            const int qi  = kh * 4 + q;           // 0..7
            const int prow = qi * 8 + warp;       // 0..63 local adj row
            const int4* asrc = (const int4*)(adj + (size_t)(m0 + prow) * N_);
            int4 av[4];
#pragma unroll
            for (int sp = 0; sp < 4; sp++) av[sp] = asrc[sp * 32 + lane];

            // --- FFMA quarter-chunk: 16 k values ---
#pragma unroll
            for (int kk = 0; kk < 16; kk++) {
                int k = q * 16 + kk;
                float4 wv = *(const float4*)(Ws + (kh * 64 + k) * 64 + tx * 4);
                float x0 = Xs[(ty * 4 + 0) * 68 + k];
                float x1 = Xs[(ty * 4 + 1) * 68 + k];
                float x2 = Xs[(ty * 4 + 2) * 68 + k];
                float x3 = Xs[(ty * 4 + 3) * 68 + k];
                acc[0][0] += x0 * wv.x; acc[0][1] += x0 * wv.y; acc[0][2] += x0 * wv.z; acc[0][3] += x0 * wv.w;
                acc[1][0] += x1 * wv.x; acc[1][1] += x1 * wv.y; acc[1][2] += x1 * wv.z; acc[1][3] += x1 * wv.w;
                acc[2][0] += x2 * wv.x; acc[2][1] += x2 * wv.y; acc[2][2] += x2 * wv.z; acc[2][3] += x2 * wv.w;
                acc[3][0] += x3 * wv.x; acc[3][1] += x3 * wv.y; acc[3][2] += x3 * wv.z; acc[3][3] += x3 * wv.w;
            }

            // --- pack + store mask row ---
#pragma unroll
            for (int sp = 0; sp < 4; sp++) {
                uint32_t nib = (uint32_t)(av[sp].x > 0) | ((uint32_t)(av[sp].y > 0) << 1)
                             | ((uint32_t)(av[sp].z > 0) << 2) | ((uint32_t)(av[sp].w > 0) << 3);
                uint32_t v = nib << ((lane & 7) * 4);
                v |= __shfl_xor_sync(0xffffffffu, v, 1);
                v |= __shfl_xor_sync(0xffffffffu, v, 2);
                v |= __shfl_xor_sync(0xffffffffu, v, 4);
                if ((lane & 7) == 0)
                    g_mask[(size_t)(m0 + prow) * 16 + sp * 4 + (lane >> 3)] = v;
            }
        }
        __syncthreads();
    }

    float as[4], ad[4];
#pragma unroll
    for (int c = 0; c < 4; c++) {
        as[c] = __ldg(a + tx * 4 + c);
        ad[c] = __ldg(a + 64 + tx * 4 + c);
    }

#pragma unroll
    for (int i = 0; i < 4; i++) {
        size_t row = (size_t)(m0 + ty * 4 + i);
        __half hv[4];
#pragma unroll
        for (int c = 0; c < 4; c++) hv[c] = __float2half(acc[i][c]);
        *(uint2*)(g_hh + row * FOUT + tx * 4) = *(uint2*)hv;

        float sp = acc[i][0] * as[0] + acc[i][1] * as[1] + acc[i][2] * as[2] + acc[i][3] * as[3];
        float tp = acc[i][0] * ad[0] + acc[i][1] * ad[1] + acc[i][2] * ad[2] + acc[i][3] * ad[3];
#pragma unroll
        for (int o = 8; o; o >>= 1) {
            sp += __shfl_xor_sync(0xffffffffu, sp, o);
            tp += __shfl_xor_sync(0xffffffffu, tp, o);
        }
        if (tx == 0) { g_s[row] = sp * L2E; g_t[row] = tp * L2E; }  // log2 domain
    }
}

// ---------------------------------------------------------------------------
// Kernel B: chunked masked-softmax (bitmask from smem, exp2 domain) +
// tensor-core att@h. Pipelined hs cp.async + double-buffered attC.
// ---------------------------------------------------------------------------
#define ATT_S 72
#define HS_S  72

__global__ void __launch_bounds__(256, 5) attn_kernel(float* __restrict__ out)
{
    extern __shared__ char smraw[];
    float* t_sh = (float*)smraw;                   // 512 (log2-scaled t)
    float* inv  = t_sh + 512;                      // 32
    float* wmax = inv + 32;                        // 8
    uint32_t* mask_sh = (uint32_t*)(wmax + 8);     // 32 rows x 16 words
    __half* attC = (__half*)(mask_sh + 512);       // 2 x 32 x 72
    __half* hsC  = attC + 2 * 32 * ATT_S;          // 2 x 64 x 72

    const int b    = blockIdx.y;
    const int r0   = blockIdx.x * 32;
    const int tid  = threadIdx.x;
    const int warp = tid >> 5;
    const int lane = tid & 31;

    const int ld_row = tid >> 3;
    const int ld_off = (tid & 7) * 8;
    const __half* hb = g_hh + (size_t)b * N_ * FOUT;
    const uint32_t hsBase = smem_u32(hsC);

    // prologue: stream hs chunk 0 into buf 0
    cp_async16(hsBase + (uint32_t)((ld_row)      * HS_S + ld_off) * 2, hb + (size_t)(ld_row)      * FOUT + ld_off);
    cp_async16(hsBase + (uint32_t)((ld_row + 32) * HS_S + ld_off) * 2, hb + (size_t)(ld_row + 32) * FOUT + ld_off);
    CP_COMMIT();

    mask_sh[tid]       = g_mask[((size_t)b * N_ + r0) * 16 + tid];
    mask_sh[tid + 256] = g_mask[((size_t)b * N_ + r0) * 16 + tid + 256];

    float t0 = g_t[b * N_ + tid];
    float t1 = g_t[b * N_ + tid + 256];
    t_sh[tid]       = t0;
    t_sh[tid + 256] = t1;

    float m2 = fmaxf(t0, t1);
#pragma unroll
    for (int o = 16; o; o >>= 1) m2 = fmaxf(m2, __shfl_xor_sync(0xffffffffu, m2, o));
    if (lane == 0) wmax[warp] = m2;
    __syncthreads();
    const float maxT = fmaxf(fmaxf(fmaxf(wmax[0], wmax[1]), fmaxf(wmax[2], wmax[3])),
                             fmaxf(fmaxf(wmax[4], wmax[5]), fmaxf(wmax[6], wmax[7])));

    float s_r[4], mx_r[4], sum_r[4];
#pragma unroll
    for (int rr = 0; rr < 4; rr++) {
        int grow = r0 + warp * 4 + rr;
        float s  = g_s[b * N_ + grow];
        float pm = s + maxT;
        s_r[rr]  = s;
        mx_r[rr] = pm > 0.f ? pm : 0.2f * pm;    // log2-domain row max (leaky homogeneous)
        sum_r[rr] = 0.f;
    }

    const int mtile  = warp >> 2;
    const int ntg0   = (warp & 3) * 2;
    const int lrow16 = lane & 15;
    const int lhalf  = lane >> 4;
    const uint32_t aBase = smem_u32(attC + (mtile * 16 + lrow16) * ATT_S + lhalf * 8);
    const uint32_t bBase = smem_u32(hsC + lrow16 * HS_S + (ntg0 + lhalf) * 8);
    const uint32_t attBufB = (uint32_t)(32 * ATT_S) * 2;
    const uint32_t hsBufB  = (uint32_t)(64 * HS_S) * 2;

    float acc0[4] = {0.f, 0.f, 0.f, 0.f};
    float acc1[4] = {0.f, 0.f, 0.f, 0.f};

    const uint32_t mword = lane >> 4;
    const uint32_t mbit  = (lane & 15) * 2;

    for (int c = 0; c < 8; c++) {
        const int k0  = c * 64;
        const int buf = c & 1;

        __half* attW = attC + buf * 32 * ATT_S;
#pragma unroll
        for (int rr = 0; rr < 4; rr++) {
            int r = warp * 4 + rr;
            uint32_t mw = mask_sh[r * 16 + c * 2 + mword];
            float2 tv = *(const float2*)(t_sh + k0 + lane * 2);
            float e0 = s_r[rr] + tv.x; e0 = fmaxf(e0, 0.2f * e0);
            float e1 = s_r[rr] + tv.y; e1 = fmaxf(e1, 0.2f * e1);
            float w0 = ((mw >> mbit) & 1u)       ? ex2f(e0 - mx_r[rr]) : 0.f;
            float w1 = ((mw >> (mbit + 1)) & 1u) ? ex2f(e1 - mx_r[rr]) : 0.f;
            sum_r[rr] += w0 + w1;
            __half2 p = __floats2half2_rn(w0, w1);
            *(uint32_t*)(attW + r * ATT_S + lane * 2) = *(uint32_t*)&p;
        }

        CP_WAIT0();
        __syncthreads();

        if (c < 7) {
            const __half* hn = hb + (size_t)(k0 + 64) * FOUT;
            uint32_t dst = hsBase + (1 - buf) * hsBufB;
            cp_async16(dst + (uint32_t)((ld_row)      * HS_S + ld_off) * 2, hn + (size_t)(ld_row)      * FOUT + ld_off);
            cp_async16(dst + (uint32_t)((ld_row + 32) * HS_S + ld_off) * 2, hn + (size_t)(ld_row + 32) * FOUT + ld_off);
            CP_COMMIT();
        }

        const uint32_t aA = aBase + buf * attBufB;
        const uint32_t bA = bBase + buf * hsBufB;
#pragma unroll
        for (int ks = 0; ks < 4; ks++) {
            const uint32_t aOff = (uint32_t)(ks * 16) * 2;
            const uint32_t bOff = (uint32_t)(ks * 16) * HS_S * 2;
            uint32_t av[4], b0, b1, b2, b3;
            ldsm_x4(av[0], av[1], av[2], av[3], aA + aOff);
            ldsm_x4t(b0, b1, b2, b3, bA + bOff);
            mma16816(acc0, av, b0, b1);
            mma16816(acc1, av, b2, b3);
        }
    }

#pragma unroll
    for (int rr = 0; rr < 4; rr++) {
        float sum = sum_r[rr];
#pragma unroll
        for (int o = 16; o; o >>= 1) sum += __shfl_xor_sync(0xffffffffu, sum, o);
        if (lane == 0) inv[warp * 4 + rr] = 1.0f / sum;
    }
    __syncthreads();

    const int gid = lane >> 2;
    const int tg  = lane & 3;
    const int rA  = mtile * 16 + gid;
    const int rB  = rA + 8;
    const float invA = inv[rA];
    const float invB = inv[rB];

#pragma unroll
    for (int nt = 0; nt < 2; nt++) {
        float* acc = nt ? acc1 : acc0;
        int col = (ntg0 + nt) * 8 + tg * 2;
        float v;
        float2 oA, oB;
        v = acc[0] * invA; oA.x = v > 0.f ? v : 0.01f * v;
        v = acc[1] * invA; oA.y = v > 0.f ? v : 0.01f * v;
        v = acc[2] * invB; oB.x = v > 0.f ? v : 0.01f * v;
        v = acc[3] * invB; oB.y = v > 0.f ? v : 0.01f * v;
        *(float2*)(out + ((size_t)b * N_ + r0 + rA) * FOUT + col) = oA;
        *(float2*)(out + ((size_t)b * N_ + r0 + rB) * FOUT + col) = oB;
    }
}

// ---------------------------------------------------------------------------
extern "C" void kernel_launch(void* const* d_in, const int* in_sizes, int n_in,
                              void* d_out, int out_size)
{
    const float* X   = (const float*)d_in[0];
    const int*   adj = (const int*)  d_in[1];
    const float* W   = (const float*)d_in[2];
    const float* a   = (const float*)d_in[3];
    float* out = (float*)d_out;

    size_t smA = (size_t)(64 * 68 + 128 * 64) * sizeof(float);   // ~50 KB
    cudaFuncSetAttribute(gemm1_kernel, cudaFuncAttributeMaxDynamicSharedMemorySize, (int)smA);
    gemm1_kernel<<<(B_ * N_) / 64, 256, smA>>>(X, W, a, adj);

    size_t smB = (512 + 32 + 8) * sizeof(float) + 512 * sizeof(uint32_t)
               + (size_t)(2 * 32 * ATT_S + 2 * 64 * HS_S) * sizeof(__half);  // ~31.9 KB
    cudaFuncSetAttribute(attn_kernel, cudaFuncAttributeMaxDynamicSharedMemorySize, (int)smB);
    attn_kernel<<<dim3(N_ / 32, B_), 256, smB>>>(out);
}

// round 9
// speedup vs baseline: 1.3304x; 1.3101x over previous
#include <cuda_runtime.h>
#include <cuda_fp16.h>
#include <cstdint>

#define B_   128
#define N_   512
#define FIN  128
#define FOUT 64
#define L2E  1.4426950408889634f

// Scratch (allocation-free rule: __device__ globals)
__device__ __half g_hh[B_ * N_ * FOUT];   // h fp16, row-major [row][f]
__device__ float  g_s[B_ * N_];           // s * log2(e)
__device__ float  g_t[B_ * N_];           // t * log2(e)

// ---------------------------------------------------------------------------
// PTX helpers
// ---------------------------------------------------------------------------
__device__ __forceinline__ uint32_t smem_u32(const void* p) {
    return (uint32_t)__cvta_generic_to_shared(p);
}
__device__ __forceinline__ float ex2f(float x) {
    float y;
    asm("ex2.approx.f32 %0, %1;\n" : "=f"(y) : "f"(x));
    return y;
}
__device__ __forceinline__ void ldsm_x4(uint32_t& r0, uint32_t& r1, uint32_t& r2, uint32_t& r3, uint32_t addr) {
    asm volatile("ldmatrix.sync.aligned.m8n8.x4.shared.b16 {%0,%1,%2,%3}, [%4];\n"
                 : "=r"(r0), "=r"(r1), "=r"(r2), "=r"(r3) : "r"(addr));
}
__device__ __forceinline__ void ldsm_x4t(uint32_t& r0, uint32_t& r1, uint32_t& r2, uint32_t& r3, uint32_t addr) {
    asm volatile("ldmatrix.sync.aligned.m8n8.x4.trans.shared.b16 {%0,%1,%2,%3}, [%4];\n"
                 : "=r"(r0), "=r"(r1), "=r"(r2), "=r"(r3) : "r"(addr));
}
__device__ __forceinline__ void mma16816(float* d, const uint32_t* a, uint32_t b0, uint32_t b1) {
    asm volatile("mma.sync.aligned.m16n8k16.row.col.f32.f16.f16.f32 "
                 "{%0,%1,%2,%3},{%4,%5,%6,%7},{%8,%9},{%0,%1,%2,%3};\n"
                 : "+f"(d[0]), "+f"(d[1]), "+f"(d[2]), "+f"(d[3])
                 : "r"(a[0]), "r"(a[1]), "r"(a[2]), "r"(a[3]), "r"(b0), "r"(b1));
}
__device__ __forceinline__ void cp_async16(uint32_t saddr, const void* gptr) {
    asm volatile("cp.async.cg.shared.global [%0], [%1], 16;\n" :: "r"(saddr), "l"(gptr));
}
#define CP_COMMIT() asm volatile("cp.async.commit_group;\n" ::: "memory")
#define CP_WAIT0()  asm volatile("cp.async.wait_group 0;\n" ::: "memory")

// ---------------------------------------------------------------------------
// Kernel A: h = X @ W on tensor cores (fp16 3-term split: hihi + hilo + lohi).
// Block: 128 rows x 64 cols, K=128 in 2 halves. 8 warps, one m16 tile each.
// Epilogue: h fp16 store + fused s,t (scaled by log2e).
// ---------------------------------------------------------------------------
#define XS 72
#define WS 72

__global__ void __launch_bounds__(256, 3) gemm1_kernel(
    const float* __restrict__ X, const float* __restrict__ W,
    const float* __restrict__ a)
{
    extern __shared__ __half smh[];
    __half* Xhi = smh;                 // 128 x 72
    __half* Xlo = Xhi + 128 * XS;      // 128 x 72
    __half* Whi = Xlo + 128 * XS;      // 64 x 72
    __half* Wlo = Whi + 64 * WS;       // 64 x 72

    const int tid  = threadIdx.x;
    const int warp = tid >> 5;
    const int lane = tid & 31;
    const int m0   = blockIdx.x * 128;

    const int lrow16 = lane & 15;
    const int lhalf  = lane >> 4;
    const uint32_t aHi = smem_u32(Xhi + (warp * 16 + lrow16) * XS + lhalf * 8);
    const uint32_t aLo = smem_u32(Xlo + (warp * 16 + lrow16) * XS + lhalf * 8);
    const uint32_t bHi = smem_u32(Whi + lrow16 * WS + lhalf * 8);
    const uint32_t bLo = smem_u32(Wlo + lrow16 * WS + lhalf * 8);

    float acc[8][4] = {};

#pragma unroll
    for (int kh = 0; kh < 2; kh++) {
#pragma unroll
        for (int p = 0; p < 8; p++) {
            int u  = p * 256 + tid;
            int r  = u >> 4;
            int c4 = (u & 15) * 4;
            float4 xv = *(const float4*)(X + (size_t)(m0 + r) * FIN + kh * 64 + c4);
            __half h4[4], l4[4];
            h4[0] = __float2half(xv.x); l4[0] = __float2half(xv.x - __half2float(h4[0]));
            h4[1] = __float2half(xv.y); l4[1] = __float2half(xv.y - __half2float(h4[1]));
            h4[2] = __float2half(xv.z); l4[2] = __float2half(xv.z - __half2float(h4[2]));
            h4[3] = __float2half(xv.w); l4[3] = __float2half(xv.w - __half2float(h4[3]));
            *(uint2*)(Xhi + r * XS + c4) = *(uint2*)h4;
            *(uint2*)(Xlo + r * XS + c4) = *(uint2*)l4;
        }
#pragma unroll
        for (int p = 0; p < 4; p++) {
            int u  = p * 256 + tid;
            int k  = u >> 4;
            int c4 = (u & 15) * 4;
            float4 wv = *(const float4*)(W + (size_t)(kh * 64 + k) * FOUT + c4);
            __half h4[4], l4[4];
            h4[0] = __float2half(wv.x); l4[0] = __float2half(wv.x - __half2float(h4[0]));
            h4[1] = __float2half(wv.y); l4[1] = __float2half(wv.y - __half2float(h4[1]));
            h4[2] = __float2half(wv.z); l4[2] = __float2half(wv.z - __half2float(h4[2]));
            h4[3] = __float2half(wv.w); l4[3] = __float2half(wv.w - __half2float(h4[3]));
            *(uint2*)(Whi + k * WS + c4) = *(uint2*)h4;
            *(uint2*)(Wlo + k * WS + c4) = *(uint2*)l4;
        }
        __syncthreads();

#pragma unroll
        for (int ks = 0; ks < 4; ks++) {
            const uint32_t aOff = (uint32_t)(ks * 16) * 2;
            const uint32_t bOff = (uint32_t)(ks * 16) * WS * 2;
            uint32_t ah[4], al[4];
            ldsm_x4(ah[0], ah[1], ah[2], ah[3], aHi + aOff);
            ldsm_x4(al[0], al[1], al[2], al[3], aLo + aOff);
#pragma unroll
            for (int ng = 0; ng < 4; ng++) {
                uint32_t bh[4], bl[4];
                ldsm_x4t(bh[0], bh[1], bh[2], bh[3], bHi + bOff + ng * 32);
                ldsm_x4t(bl[0], bl[1], bl[2], bl[3], bLo + bOff + ng * 32);
                mma16816(acc[ng * 2],     ah, bh[0], bh[1]);
                mma16816(acc[ng * 2],     ah, bl[0], bl[1]);
                mma16816(acc[ng * 2],     al, bh[0], bh[1]);
                mma16816(acc[ng * 2 + 1], ah, bh[2], bh[3]);
                mma16816(acc[ng * 2 + 1], ah, bl[2], bl[3]);
                mma16816(acc[ng * 2 + 1], al, bh[2], bh[3]);
            }
        }
        __syncthreads();
    }

    // Epilogue: h fp16 store + fused s/t (log2 domain)
    const int gid = lane >> 2;
    const int tg  = lane & 3;
    const size_t rA = (size_t)m0 + warp * 16 + gid;
    const size_t rB = rA + 8;

    float spA = 0.f, tpA = 0.f, spB = 0.f, tpB = 0.f;
#pragma unroll
    for (int j = 0; j < 8; j++) {
        int col = j * 8 + tg * 2;
        float a0 = __ldg(a + col), a1 = __ldg(a + col + 1);
        float d0 = __ldg(a + 64 + col), d1 = __ldg(a + 64 + col + 1);

        __half2 hA = __floats2half2_rn(acc[j][0], acc[j][1]);
        __half2 hB = __floats2half2_rn(acc[j][2], acc[j][3]);
        *(uint32_t*)(g_hh + rA * FOUT + col) = *(uint32_t*)&hA;
        *(uint32_t*)(g_hh + rB * FOUT + col) = *(uint32_t*)&hB;

        spA += acc[j][0] * a0 + acc[j][1] * a1;
        tpA += acc[j][0] * d0 + acc[j][1] * d1;
        spB += acc[j][2] * a0 + acc[j][3] * a1;
        tpB += acc[j][2] * d0 + acc[j][3] * d1;
    }
#pragma unroll
    for (int o = 1; o <= 2; o <<= 1) {
        spA += __shfl_xor_sync(0xffffffffu, spA, o);
        tpA += __shfl_xor_sync(0xffffffffu, tpA, o);
        spB += __shfl_xor_sync(0xffffffffu, spB, o);
        tpB += __shfl_xor_sync(0xffffffffu, tpB, o);
    }
    if (tg == 0) {
        g_s[rA] = spA * L2E; g_t[rA] = tpA * L2E;
        g_s[rB] = spB * L2E; g_t[rB] = tpB * L2E;
    }
}

// ---------------------------------------------------------------------------
// Kernel B: chunked masked-softmax (inline adj, exp2 domain) + tensor-core
// att@h. Pipelined: adj reg-prefetch, hs cp.async double-buffer, attC
// double-buffer, 1 barrier per chunk.
// ---------------------------------------------------------------------------
#define ATT_S 72
#define HS_S  72

__global__ void __launch_bounds__(256, 4) attn_kernel(
    const int* __restrict__ adj, float* __restrict__ out)
{
    extern __shared__ char smraw[];
    float* t_sh = (float*)smraw;                 // 512 (log2-scaled t)
    float* inv  = t_sh + 512;                    // 32
    float* wmax = inv + 32;                      // 8
    __half* attC = (__half*)(wmax + 8);          // 2 x 32 x 72
    __half* hsC  = attC + 2 * 32 * ATT_S;        // 2 x 64 x 72

    const int b    = blockIdx.y;
    const int r0   = blockIdx.x * 32;
    const int tid  = threadIdx.x;
    const int warp = tid >> 5;
    const int lane = tid & 31;

    const int ld_row = tid >> 3;
    const int ld_off = (tid & 7) * 8;
    const __half* hb = g_hh + (size_t)b * N_ * FOUT;
    const uint32_t hsBase = smem_u32(hsC);

    // prologue: stream hs chunk 0 into buf 0
    cp_async16(hsBase + (uint32_t)((ld_row)      * HS_S + ld_off) * 2, hb + (size_t)(ld_row)      * FOUT + ld_off);
    cp_async16(hsBase + (uint32_t)((ld_row + 32) * HS_S + ld_off) * 2, hb + (size_t)(ld_row + 32) * FOUT + ld_off);
    CP_COMMIT();

    float t0 = g_t[b * N_ + tid];
    float t1 = g_t[b * N_ + tid + 256];
    t_sh[tid]       = t0;
    t_sh[tid + 256] = t1;

    float m2 = fmaxf(t0, t1);
#pragma unroll
    for (int o = 16; o; o >>= 1) m2 = fmaxf(m2, __shfl_xor_sync(0xffffffffu, m2, o));
    if (lane == 0) wmax[warp] = m2;
    __syncthreads();
    const float maxT = fmaxf(fmaxf(fmaxf(wmax[0], wmax[1]), fmaxf(wmax[2], wmax[3])),
                             fmaxf(fmaxf(wmax[4], wmax[5]), fmaxf(wmax[6], wmax[7])));

    float s_r[4], mx_r[4], sum_r[4];
#pragma unroll
    for (int rr = 0; rr < 4; rr++) {
        int grow = r0 + warp * 4 + rr;
        float s  = g_s[b * N_ + grow];
        float pm = s + maxT;
        s_r[rr]  = s;
        mx_r[rr] = pm > 0.f ? pm : 0.2f * pm;   // log2-domain row max (leaky homogeneous)
        sum_r[rr] = 0.f;
    }

    const int mtile  = warp >> 2;
    const int ntg0   = (warp & 3) * 2;
    const int lrow16 = lane & 15;
    const int lhalf  = lane >> 4;
    const uint32_t aBase = smem_u32(attC + (mtile * 16 + lrow16) * ATT_S + lhalf * 8);
    const uint32_t bBase = smem_u32(hsC + lrow16 * HS_S + (ntg0 + lhalf) * 8);
    const uint32_t attBufB = (uint32_t)(32 * ATT_S) * 2;
    const uint32_t hsBufB  = (uint32_t)(64 * HS_S) * 2;

    float acc0[4] = {0.f, 0.f, 0.f, 0.f};
    float acc1[4] = {0.f, 0.f, 0.f, 0.f};

    const int* adjB = adj + ((size_t)b * N_ + r0) * N_;

    // adj prefetch for chunk 0
    int2 avc[4], avn[4];
#pragma unroll
    for (int rr = 0; rr < 4; rr++)
        avc[rr] = *(const int2*)(adjB + (size_t)(warp * 4 + rr) * N_ + lane * 2);

    for (int c = 0; c < 8; c++) {
        const int k0  = c * 64;
        const int buf = c & 1;

        // issue adj prefetch for chunk c+1
        if (c < 7) {
#pragma unroll
            for (int rr = 0; rr < 4; rr++)
                avn[rr] = *(const int2*)(adjB + (size_t)(warp * 4 + rr) * N_ + k0 + 64 + lane * 2);
        }

        // phase-1: weights for 32 rows x 64 cols -> attC[buf]
        __half* attW = attC + buf * 32 * ATT_S;
#pragma unroll
        for (int rr = 0; rr < 4; rr++) {
            int r = warp * 4 + rr;
            float2 tv = *(const float2*)(t_sh + k0 + lane * 2);
            float e0 = s_r[rr] + tv.x; e0 = fmaxf(e0, 0.2f * e0);
            float e1 = s_r[rr] + tv.y; e1 = fmaxf(e1, 0.2f * e1);
            float w0 = avc[rr].x > 0 ? ex2f(e0 - mx_r[rr]) : 0.f;
            float w1 = avc[rr].y > 0 ? ex2f(e1 - mx_r[rr]) : 0.f;
            sum_r[rr] += w0 + w1;
            __half2 p = __floats2half2_rn(w0, w1);
            *(uint32_t*)(attW + r * ATT_S + lane * 2) = *(uint32_t*)&p;
        }

        CP_WAIT0();            // hs[c] landed
        __syncthreads();       // attC[buf] + hs[buf] visible

        // stream hs chunk c+1 into the other buffer
        if (c < 7) {
            const __half* hn = hb + (size_t)(k0 + 64) * FOUT;
            uint32_t dst = hsBase + (1 - buf) * hsBufB;
            cp_async16(dst + (uint32_t)((ld_row)      * HS_S + ld_off) * 2, hn + (size_t)(ld_row)      * FOUT + ld_off);
            cp_async16(dst + (uint32_t)((ld_row + 32) * HS_S + ld_off) * 2, hn + (size_t)(ld_row + 32) * FOUT + ld_off);
            CP_COMMIT();
        }

        // MMA: C[32,64] += attC[buf] @ hsC[buf]
        const uint32_t aA = aBase + buf * attBufB;
        const uint32_t bA = bBase + buf * hsBufB;
#pragma unroll
        for (int ks = 0; ks < 4; ks++) {
            const uint32_t aOff = (uint32_t)(ks * 16) * 2;
            const uint32_t bOff = (uint32_t)(ks * 16) * HS_S * 2;
            uint32_t av[4], b0, b1, b2, b3;
            ldsm_x4(av[0], av[1], av[2], av[3], aA + aOff);
            ldsm_x4t(b0, b1, b2, b3, bA + bOff);
            mma16816(acc0, av, b0, b1);
            mma16816(acc1, av, b2, b3);
        }

#pragma unroll
        for (int rr = 0; rr < 4; rr++) avc[rr] = avn[rr];
    }

    // row sums -> inv
#pragma unroll
    for (int rr = 0; rr < 4; rr++) {
        float sum = sum_r[rr];
#pragma unroll
        for (int o = 16; o; o >>= 1) sum += __shfl_xor_sync(0xffffffffu, sum, o);
        if (lane == 0) inv[warp * 4 + rr] = 1.0f / sum;
    }
    __syncthreads();

    // epilogue: normalize + leaky_relu(0.01) + store
    const int gid = lane >> 2;
    const int tg  = lane & 3;
    const int rA  = mtile * 16 + gid;
    const int rB  = rA + 8;
    const float invA = inv[rA];
    const float invB = inv[rB];

#pragma unroll
    for (int nt = 0; nt < 2; nt++) {
        float* acc = nt ? acc1 : acc0;
        int col = (ntg0 + nt) * 8 + tg * 2;
        float v;
        float2 oA, oB;
        v = acc[0] * invA; oA.x = v > 0.f ? v : 0.01f * v;
        v = acc[1] * invA; oA.y = v > 0.f ? v : 0.01f * v;
        v = acc[2] * invB; oB.x = v > 0.f ? v : 0.01f * v;
        v = acc[3] * invB; oB.y = v > 0.f ? v : 0.01f * v;
        *(float2*)(out + ((size_t)b * N_ + r0 + rA) * FOUT + col) = oA;
        *(float2*)(out + ((size_t)b * N_ + r0 + rB) * FOUT + col) = oB;
    }
}

// ---------------------------------------------------------------------------
extern "C" void kernel_launch(void* const* d_in, const int* in_sizes, int n_in,
                              void* d_out, int out_size)
{
    const float* X   = (const float*)d_in[0];
    const int*   adj = (const int*)  d_in[1];
    const float* W   = (const float*)d_in[2];
    const float* a   = (const float*)d_in[3];
    float* out = (float*)d_out;

    size_t smA = (size_t)(2 * 128 * XS + 2 * 64 * WS) * sizeof(__half);   // 55.3 KB
    cudaFuncSetAttribute(gemm1_kernel, cudaFuncAttributeMaxDynamicSharedMemorySize, (int)smA);
    gemm1_kernel<<<(B_ * N_) / 128, 256, smA>>>(X, W, a);

    size_t smB = (512 + 32 + 8) * sizeof(float)
               + (size_t)(2 * 32 * ATT_S + 2 * 64 * HS_S) * sizeof(__half);  // ~29.9 KB
    cudaFuncSetAttribute(attn_kernel, cudaFuncAttributeMaxDynamicSharedMemorySize, (int)smB);
    attn_kernel<<<dim3(N_ / 32, B_), 256, smB>>>(adj, out);
}